// round 5
// baseline (speedup 1.0000x reference)
#include <cuda_runtime.h>

// ---------------------------------------------------------------------------
// Fused MHA block, tf32 tensor cores + cp.async pipelines.
//   QKV GEMM (tf32, 3-stage) -> flash attention (tf32, K-split, 2-stage) -> proj.
// Shapes: B=2, N=2048, EMBED=1024, HEADS=16, HDIM=64.
// ---------------------------------------------------------------------------

#define BATCH  2
#define SEQ    2048
#define EMBED  1024
#define HEADS  16
#define HDIM   64
#define MTOK   (BATCH * SEQ)      // 4096
#define QKVN   (3 * EMBED)        // 3072
#define SCALE  0.125f             // HDIM^-0.5

__device__ float g_Q[BATCH * HEADS * SEQ * HDIM];   // [B,H,N,Dh]
__device__ float g_K[BATCH * HEADS * SEQ * HDIM];
__device__ float g_V[BATCH * HEADS * SEQ * HDIM];
__device__ float g_O[BATCH * SEQ * EMBED];          // attention output [B,N,EMBED]

// ---------------------------------------------------------------------------
__device__ __forceinline__ unsigned f2tf(float f) {
    unsigned r;
    asm("cvt.rna.tf32.f32 %0, %1;" : "=r"(r) : "f"(f));
    return r;
}

__device__ __forceinline__ void mma_tf32(float* c, const unsigned* a, const unsigned* b) {
    asm volatile(
        "mma.sync.aligned.m16n8k8.row.col.f32.tf32.tf32.f32 "
        "{%0,%1,%2,%3}, {%4,%5,%6,%7}, {%8,%9}, {%0,%1,%2,%3};\n"
        : "+f"(c[0]), "+f"(c[1]), "+f"(c[2]), "+f"(c[3])
        : "r"(a[0]), "r"(a[1]), "r"(a[2]), "r"(a[3]),
          "r"(b[0]), "r"(b[1]));
}

__device__ __forceinline__ unsigned sptr(const void* p) {
    return (unsigned)__cvta_generic_to_shared(p);
}
#define CP_ASYNC16(dst, src) \
    asm volatile("cp.async.cg.shared.global [%0], [%1], 16;\n" :: "r"(dst), "l"(src))
#define CP_COMMIT() asm volatile("cp.async.commit_group;\n" ::: "memory")
#define CP_WAIT(n)  asm volatile("cp.async.wait_group %0;\n" :: "n"(n) : "memory")

// Load a raw fp32 smem word, convert to tf32 (RNA).
__device__ __forceinline__ unsigned ld_tf(const unsigned* p) {
    return f2tf(__uint_as_float(*p));
}

// ---------------------------------------------------------------------------
// GEMM: C[M,N] = A[M,K] @ W[N,K]^T + bias[N]   (tf32, 3-stage cp.async)
// 128x128 CTA tile, BK=32, 256 threads = 8 warps (4 M x 2 N), warp 32x64.
// Smem holds raw fp32; tf32 conversion at fragment load.
// MODE 0: scatter into g_Q/g_K/g_V.  MODE 1: write to out.
// ---------------------------------------------------------------------------
#define GSTAGES 3
#define GLDT    36                     // padded row stride (words)
#define GSTW    (2 * 128 * GLDT)       // words per stage (A tile + B tile)
#define GSMEM_BYTES (GSTAGES * GSTW * 4)

template <int MODE>
__global__ __launch_bounds__(256, 2)
void gemm_mma(const float* __restrict__ A, const float* __restrict__ W,
              const float* __restrict__ bias, float* __restrict__ out,
              int M, int N, int K)
{
    constexpr int BM = 128, BK = 32;
    extern __shared__ unsigned smg[];

    const int tid  = threadIdx.x;
    const int wid  = tid >> 5;
    const int lane = tid & 31;
    const int g    = lane >> 2;
    const int t    = lane & 3;

    const int wm0 = (wid & 3) * 32;
    const int wn0 = (wid >> 2) * 64;

    const int m0 = blockIdx.y * BM;
    const int n0 = blockIdx.x * 128;

    float acc[2][8][4];
#pragma unroll
    for (int mi = 0; mi < 2; ++mi)
#pragma unroll
        for (int nj = 0; nj < 8; ++nj)
#pragma unroll
            for (int r = 0; r < 4; ++r) acc[mi][nj][r] = 0.f;

    // Stage loader: 128 rows x 8 float4 per tile; 256 threads -> 4 f4 each per tile.
    auto load_stage = [&](int k0i, int slot) {
        unsigned* st = smg + slot * GSTW;
        const int k0 = k0i * BK;
#pragma unroll
        for (int i = 0; i < 4; ++i) {
            const int idx = tid + 256 * i;
            const int row = idx >> 3;
            const int c4  = (idx & 7) * 4;
            CP_ASYNC16(sptr(st + row * GLDT + c4),
                       &A[(size_t)(m0 + row) * K + k0 + c4]);
            CP_ASYNC16(sptr(st + BM * GLDT + row * GLDT + c4),
                       &W[(size_t)(n0 + row) * K + k0 + c4]);
        }
    };

    const int niter = K / BK;
#pragma unroll
    for (int s = 0; s < GSTAGES - 1; ++s) { load_stage(s, s); CP_COMMIT(); }

    for (int k0i = 0; k0i < niter; ++k0i) {
        CP_WAIT(GSTAGES - 2);
        __syncthreads();
        {
            const int pf = k0i + GSTAGES - 1;
            if (pf < niter) load_stage(pf, pf % GSTAGES);
            CP_COMMIT();
        }
        const unsigned* As = smg + (k0i % GSTAGES) * GSTW;
        const unsigned* Bs = As + BM * GLDT;

#pragma unroll
        for (int ks = 0; ks < BK / 8; ++ks) {
            const int kk = ks * 8;
            unsigned a[2][4], b[8][2];
#pragma unroll
            for (int mi = 0; mi < 2; ++mi) {
                const int mb = wm0 + mi * 16;
                a[mi][0] = ld_tf(&As[(mb + g)     * GLDT + kk + t]);
                a[mi][1] = ld_tf(&As[(mb + g + 8) * GLDT + kk + t]);
                a[mi][2] = ld_tf(&As[(mb + g)     * GLDT + kk + t + 4]);
                a[mi][3] = ld_tf(&As[(mb + g + 8) * GLDT + kk + t + 4]);
            }
#pragma unroll
            for (int nj = 0; nj < 8; ++nj) {
                const int nb = wn0 + nj * 8 + g;
                b[nj][0] = ld_tf(&Bs[nb * GLDT + kk + t]);
                b[nj][1] = ld_tf(&Bs[nb * GLDT + kk + t + 4]);
            }
#pragma unroll
            for (int mi = 0; mi < 2; ++mi)
#pragma unroll
                for (int nj = 0; nj < 8; ++nj)
                    mma_tf32(acc[mi][nj], a[mi], b[nj]);
        }
    }

#pragma unroll
    for (int mi = 0; mi < 2; ++mi) {
#pragma unroll
        for (int nj = 0; nj < 8; ++nj) {
#pragma unroll
            for (int r = 0; r < 4; ++r) {
                const int m = m0 + wm0 + mi * 16 + g + (r >= 2 ? 8 : 0);
                const int n = n0 + wn0 + nj * 8 + 2 * t + (r & 1);
                float v = acc[mi][nj][r] + bias[n];
                if (MODE == 0) {
                    const int which = n >> 10;
                    const int rem   = n & 1023;
                    const int h     = rem >> 6;
                    const int dh    = rem & 63;
                    const int b_    = m >> 11;
                    const int tkn   = m & 2047;
                    float* dst = (which == 0) ? g_Q : (which == 1) ? g_K : g_V;
                    dst[(((size_t)(b_ * HEADS + h) * SEQ) + tkn) * HDIM + dh] = v;
                } else {
                    out[(size_t)m * N + n] = v;
                }
            }
        }
    }
}

// ---------------------------------------------------------------------------
// Flash attention, tf32 mma, double-buffered raw K/V via cp.async.
// 1 CTA per (bh, 128 q-rows); 8 warps x (16 q-rows x 64 kv). KV tile 64.
// S = Qb@(Kb+Ks)^T with K hi/lo split computed in registers from raw fp32.
// Smem regions (LD=68 words, conflict-free (4g+t) bank permutation):
//   Qt  [128][68] tf32   |  KV[2] [128][68] raw fp32 (K rows 0-63, V rows 64-127)
//   P   [128][68] tf32
// ---------------------------------------------------------------------------
#define ALD 68
#define AST (128 * ALD)
#define ASMEM_WORDS (4 * AST)           // 34816 words = 139264 bytes
#define NKT (SEQ / 64)                  // 32

__global__ __launch_bounds__(256, 1)
void flash_attn_mma()
{
    extern __shared__ unsigned sma[];
    unsigned* Qt = sma;                 // tf32 Q (pre-scaled)
    unsigned* P  = sma + 3 * AST;       // tf32 P staging

    const int bh = blockIdx.y;
    const int q0 = blockIdx.x * 128;
    const float* Qp = g_Q + (size_t)bh * SEQ * HDIM;
    const float* Kp = g_K + (size_t)bh * SEQ * HDIM;
    const float* Vp = g_V + (size_t)bh * SEQ * HDIM;

    const int tid  = threadIdx.x;
    const int wid  = tid >> 5;
    const int lane = tid & 31;
    const int g    = lane >> 2;
    const int t    = lane & 3;
    const int arow = wid * 16;

    // KV stage loader: K tile 64x64 + V tile 64x64 fp32 = 2048 float4; 8/thread.
    auto kv_load = [&](int kt, int slot) {
        unsigned* buf = sma + (1 + slot) * AST;
#pragma unroll
        for (int i = 0; i < 8; ++i) {
            const int idx = tid + 256 * i;          // 0..2047
            const int r   = (idx >> 4) & 63;        // 64 rows
            const int c4  = (idx & 15) * 4;         // 16 float4 = 64 cols
            const float* src = ((idx < 1024) ? Kp : Vp)
                               + (size_t)(kt * 64 + r) * HDIM + c4;
            const int drow = (idx < 1024) ? r : (64 + r);
            CP_ASYNC16(sptr(buf + drow * ALD + c4), src);
        }
    };

    kv_load(0, 0); CP_COMMIT();
    kv_load(1, 1); CP_COMMIT();

    // Prologue: Q tile -> tf32 smem, pre-scaled.
#pragma unroll
    for (int it = 0; it < 8; ++it) {
        const int idx = tid + 256 * it;
        const int r = idx >> 4;
        const int c = (idx & 15) * 4;
        float4 q = *(const float4*)&Qp[(size_t)(q0 + r) * HDIM + c];
        Qt[r * ALD + c + 0] = f2tf(q.x * SCALE);
        Qt[r * ALD + c + 1] = f2tf(q.y * SCALE);
        Qt[r * ALD + c + 2] = f2tf(q.z * SCALE);
        Qt[r * ALD + c + 3] = f2tf(q.w * SCALE);
    }

    float o[8][4];
    float mrow[2] = {-1e30f, -1e30f};
    float lrow[2] = {0.f, 0.f};
#pragma unroll
    for (int nj = 0; nj < 8; ++nj)
#pragma unroll
        for (int r = 0; r < 4; ++r) o[nj][r] = 0.f;

    const unsigned FULL = 0xffffffffu;

    for (int kt = 0; kt < NKT; ++kt) {
        CP_WAIT(1);
        __syncthreads();                        // stage kt visible (and Qt on kt=0)
        const unsigned* KV = sma + (1 + (kt & 1)) * AST;

        // S = Qb @ (Kb + Ks)^T, K split hi/lo in registers.
        float s[8][4];
#pragma unroll
        for (int nj = 0; nj < 8; ++nj)
#pragma unroll
            for (int r = 0; r < 4; ++r) s[nj][r] = 0.f;

#pragma unroll
        for (int ks8 = 0; ks8 < 8; ++ks8) {
            const int kk = ks8 * 8;
            unsigned a[4];
            a[0] = Qt[(arow + g)     * ALD + kk + t];
            a[1] = Qt[(arow + g + 8) * ALD + kk + t];
            a[2] = Qt[(arow + g)     * ALD + kk + t + 4];
            a[3] = Qt[(arow + g + 8) * ALD + kk + t + 4];
#pragma unroll
            for (int nj = 0; nj < 8; ++nj) {
                const int nb = nj * 8 + g;
                const float f0 = __uint_as_float(KV[nb * ALD + kk + t]);
                const float f1 = __uint_as_float(KV[nb * ALD + kk + t + 4]);
                unsigned bb[2], bs[2];
                bb[0] = f2tf(f0);
                bb[1] = f2tf(f1);
                bs[0] = f2tf(f0 - __uint_as_float(bb[0]));
                bs[1] = f2tf(f1 - __uint_as_float(bb[1]));
                mma_tf32(s[nj], a, bb);
                mma_tf32(s[nj], a, bs);
            }
        }

        // Online softmax (two rows per thread: g and g+8).
#pragma unroll
        for (int h = 0; h < 2; ++h) {
            const int r0 = 2 * h;
            float mx = -1e30f;
#pragma unroll
            for (int nj = 0; nj < 8; ++nj)
                mx = fmaxf(mx, fmaxf(s[nj][r0], s[nj][r0 + 1]));
            mx = fmaxf(mx, __shfl_xor_sync(FULL, mx, 1));
            mx = fmaxf(mx, __shfl_xor_sync(FULL, mx, 2));
            const float mnew = fmaxf(mrow[h], mx);
            const float alpha = __expf(mrow[h] - mnew);
            float rs = 0.f;
#pragma unroll
            for (int nj = 0; nj < 8; ++nj) {
                s[nj][r0]     = __expf(s[nj][r0]     - mnew);
                s[nj][r0 + 1] = __expf(s[nj][r0 + 1] - mnew);
                rs += s[nj][r0] + s[nj][r0 + 1];
            }
            rs += __shfl_xor_sync(FULL, rs, 1);
            rs += __shfl_xor_sync(FULL, rs, 2);
            lrow[h] = alpha * lrow[h] + rs;
            mrow[h] = mnew;
#pragma unroll
            for (int nj = 0; nj < 8; ++nj) {
                o[nj][r0]     *= alpha;
                o[nj][r0 + 1] *= alpha;
            }
        }

        // Stage P (tf32). Previous PV readers finished before this iter's sync.
#pragma unroll
        for (int nj = 0; nj < 8; ++nj) {
            uint2 p0 = make_uint2(f2tf(s[nj][0]), f2tf(s[nj][1]));
            *(uint2*)&P[(arow + g) * ALD + nj * 8 + 2 * t] = p0;
            uint2 p1 = make_uint2(f2tf(s[nj][2]), f2tf(s[nj][3]));
            *(uint2*)&P[(arow + g + 8) * ALD + nj * 8 + 2 * t] = p1;
        }
        __syncthreads();                        // P visible

        // O += P @ V (V converted in registers).
#pragma unroll
        for (int ks8 = 0; ks8 < 8; ++ks8) {
            const int kk = ks8 * 8;
            unsigned a[4];
            a[0] = P[(arow + g)     * ALD + kk + t];
            a[1] = P[(arow + g + 8) * ALD + kk + t];
            a[2] = P[(arow + g)     * ALD + kk + t + 4];
            a[3] = P[(arow + g + 8) * ALD + kk + t + 4];
#pragma unroll
            for (int nj = 0; nj < 8; ++nj) {
                unsigned b[2];
                b[0] = ld_tf(&KV[(64 + kk + t)     * ALD + nj * 8 + g]);
                b[1] = ld_tf(&KV[(64 + kk + t + 4) * ALD + nj * 8 + g]);
                mma_tf32(o[nj], a, b);
            }
        }

        __syncthreads();                        // all reads of stage kt + P done
        if (kt + 2 < NKT) kv_load(kt + 2, kt & 1);
        CP_COMMIT();
    }

    // Epilogue: normalize, write to g_O [B,N,EMBED].
    const int h  = bh & (HEADS - 1);
    const int b  = bh >> 4;
    const float inv0 = 1.0f / lrow[0];
    const float inv1 = 1.0f / lrow[1];
    const int r0 = q0 + arow + g;
#pragma unroll
    for (int nj = 0; nj < 8; ++nj) {
        const int col = h * HDIM + nj * 8 + 2 * t;
        float2 v0 = make_float2(o[nj][0] * inv0, o[nj][1] * inv0);
        *(float2*)&g_O[(size_t)(b * SEQ + r0) * EMBED + col] = v0;
        float2 v1 = make_float2(o[nj][2] * inv1, o[nj][3] * inv1);
        *(float2*)&g_O[(size_t)(b * SEQ + r0 + 8) * EMBED + col] = v1;
    }
}

// ---------------------------------------------------------------------------
extern "C" void kernel_launch(void* const* d_in, const int* in_sizes, int n_in,
                              void* d_out, int out_size)
{
    const float* x      = (const float*)d_in[0];
    const float* w_qkv  = (const float*)d_in[1];
    const float* b_qkv  = (const float*)d_in[2];
    const float* w_proj = (const float*)d_in[3];
    const float* b_proj = (const float*)d_in[4];
    float* out = (float*)d_out;

    float* gO = nullptr;
    cudaGetSymbolAddress((void**)&gO, g_O);

    static bool attr_set = false;
    if (!attr_set) {
        cudaFuncSetAttribute(gemm_mma<0>,
                             cudaFuncAttributeMaxDynamicSharedMemorySize, GSMEM_BYTES);
        cudaFuncSetAttribute(gemm_mma<1>,
                             cudaFuncAttributeMaxDynamicSharedMemorySize, GSMEM_BYTES);
        cudaFuncSetAttribute(flash_attn_mma,
                             cudaFuncAttributeMaxDynamicSharedMemorySize, ASMEM_WORDS * 4);
        attr_set = true;
    }

    // 1) QKV projection (tf32 mma, 3-stage cp.async, scatter into g_Q/g_K/g_V)
    {
        dim3 grid(QKVN / 128, MTOK / 128);
        gemm_mma<0><<<grid, 256, GSMEM_BYTES>>>(x, w_qkv, b_qkv, nullptr, MTOK, QKVN, EMBED);
    }
    // 2) Flash attention (tf32 mma, double-buffered KV) -> g_O
    {
        dim3 grid(SEQ / 128, BATCH * HEADS);
        flash_attn_mma<<<grid, 256, ASMEM_WORDS * 4>>>();
    }
    // 3) Output projection (tf32 mma)
    {
        dim3 grid(EMBED / 128, MTOK / 128);
        gemm_mma<1><<<grid, 256, GSMEM_BYTES>>>(gO, w_proj, b_proj, out, MTOK, EMBED, EMBED);
    }
}

// round 6
// speedup vs baseline: 1.0662x; 1.0662x over previous
#include <cuda_runtime.h>

// ---------------------------------------------------------------------------
// Fused MHA block, tf32 mma.sync with fragment-major smem + cp.async pipelines.
// Shapes: B=2, N=2048, EMBED=1024, HEADS=16, HDIM=64.
// ---------------------------------------------------------------------------

#define BATCH  2
#define SEQ    2048
#define EMBED  1024
#define HEADS  16
#define HDIM   64
#define MTOK   (BATCH * SEQ)      // 4096
#define QKVN   (3 * EMBED)        // 3072
#define SCALE  0.125f             // HDIM^-0.5

__device__ float g_Q[BATCH * HEADS * SEQ * HDIM];   // [B,H,N,Dh]
__device__ float g_K[BATCH * HEADS * SEQ * HDIM];
__device__ float g_V[BATCH * HEADS * SEQ * HDIM];
__device__ float g_O[BATCH * SEQ * EMBED];          // attention output [B,N,EMBED]

// ---------------------------------------------------------------------------
__device__ __forceinline__ unsigned f2tf(float f) {
    unsigned r;
    asm("cvt.rna.tf32.f32 %0, %1;" : "=r"(r) : "f"(f));
    return r;
}

__device__ __forceinline__ void mma_tf32(float* c, const unsigned* a, const unsigned* b) {
    asm volatile(
        "mma.sync.aligned.m16n8k8.row.col.f32.tf32.tf32.f32 "
        "{%0,%1,%2,%3}, {%4,%5,%6,%7}, {%8,%9}, {%0,%1,%2,%3};\n"
        : "+f"(c[0]), "+f"(c[1]), "+f"(c[2]), "+f"(c[3])
        : "r"(a[0]), "r"(a[1]), "r"(a[2]), "r"(a[3]),
          "r"(b[0]), "r"(b[1]));
}

__device__ __forceinline__ unsigned sptr(const void* p) {
    return (unsigned)__cvta_generic_to_shared(p);
}
#define CP_ASYNC16(dst, src) \
    asm volatile("cp.async.cg.shared.global [%0], [%1], 16;\n" :: "r"(dst), "l"(src))
#define CP_COMMIT() asm volatile("cp.async.commit_group;\n" ::: "memory")
#define CP_WAIT1()  asm volatile("cp.async.wait_group 1;\n" ::: "memory")

// Fragment-major addressing.
// A-frag (m16n8k8 A operand, element [r][c], r=m, c=k):
//   group = m16*KS + ks (stride AGS=132 words), slot = (g*4+t)*4 + hi + 2*c4
//   reader: LDS.128 at group*132 + lane*4 -> {a0,a1,a2,a3}
// B-frag (element [n][c]):
//   group = n8*KS + ks (stride BGS=66 words), slot = (g*4+t)*2 + c4
//   reader: LDS.64 at group*66 + lane*2 -> {b0,b1}
#define AGS 132
#define BGS 66

// ---------------------------------------------------------------------------
// GEMM: C[M,N] = A[M,K] @ W[N,K]^T + bias[N]
// 128x128 tile, BK=32, 256 thr, 8 warps (4M x 2N), warp 32x64.
// Smem: raw stages[2] (A 4096 + B 4096 words each) | Afrag 4224 | Bfrag 4224.
// ---------------------------------------------------------------------------
#define G_STG0  0
#define G_STGW  8192
#define G_AF    (2 * G_STGW)            // 16384
#define G_BF    (G_AF + 32 * AGS)       // 16384 + 4224 = 20608
#define G_WORDS (G_BF + 64 * BGS)       // 24832 words = 99328 B

template <int MODE>
__global__ __launch_bounds__(256, 2)
void gemm_mma(const float* __restrict__ A, const float* __restrict__ W,
              const float* __restrict__ bias, float* __restrict__ out,
              int M, int N, int K)
{
    extern __shared__ unsigned smg[];
    unsigned* AF = smg + G_AF;
    unsigned* BF = smg + G_BF;

    const int tid  = threadIdx.x;
    const int wid  = tid >> 5;
    const int lane = tid & 31;
    const int g    = lane >> 2;
    const int t    = lane & 3;

    const int m0 = blockIdx.y * 128;
    const int n0 = blockIdx.x * 128;

    float acc[2][8][4];
#pragma unroll
    for (int mi = 0; mi < 2; ++mi)
#pragma unroll
        for (int nj = 0; nj < 8; ++nj)
#pragma unroll
            for (int r = 0; r < 4; ++r) acc[mi][nj][r] = 0.f;

    // Raw stage load: A tile 128x32 (1024 f4) + B tile 128x32 (1024 f4).
    auto load_stage = [&](int k0i, int slot) {
        unsigned* st = smg + slot * G_STGW;
        const int k0 = k0i * 32;
#pragma unroll
        for (int i = 0; i < 8; ++i) {
            const int idx = tid + 256 * i;           // 0..2047
            const int f   = idx & 1023;
            const int row = f >> 3;
            const int c4  = (f & 7) * 4;
            if (idx < 1024)
                CP_ASYNC16(sptr(st + row * 32 + c4),
                           &A[(size_t)(m0 + row) * K + k0 + c4]);
            else
                CP_ASYNC16(sptr(st + 4096 + row * 32 + c4),
                           &W[(size_t)(n0 + row) * K + k0 + c4]);
        }
    };

    const int niter = K / 32;
    load_stage(0, 0); CP_COMMIT();

    for (int k0i = 0; k0i < niter; ++k0i) {
        if (k0i + 1 < niter) load_stage(k0i + 1, (k0i + 1) & 1);
        CP_COMMIT();
        CP_WAIT1();
        __syncthreads();                 // stage k0i ready; frag free (prev mma done)

        // Convert pass: raw fp32 -> tf32 fragment-major.
        {
            const unsigned* st = smg + (k0i & 1) * G_STGW;
#pragma unroll
            for (int i = 0; i < 8; ++i) {
                const int idx = tid + 256 * i;       // 0..2047
                const int f   = idx & 1023;
                const int r   = f >> 3;
                const int c   = (f & 7) * 4;         // ks,c4 fixed within f4
                const int ks  = c >> 3;
                const int c4  = (c >> 2) & 1;
                if (idx < 1024) {
                    uint4 v = *(const uint4*)&st[r * 32 + c];
                    const int m16 = r >> 4, hi = (r >> 3) & 1, gg = r & 7;
                    unsigned* base = AF + (m16 * 4 + ks) * AGS + gg * 16 + hi + 2 * c4;
                    base[0]  = f2tf(__uint_as_float(v.x));
                    base[4]  = f2tf(__uint_as_float(v.y));
                    base[8]  = f2tf(__uint_as_float(v.z));
                    base[12] = f2tf(__uint_as_float(v.w));
                } else {
                    uint4 v = *(const uint4*)&st[4096 + r * 32 + c];
                    const int n8 = r >> 3, gg = r & 7;
                    unsigned* base = BF + (n8 * 4 + ks) * BGS + gg * 8 + c4;
                    base[0] = f2tf(__uint_as_float(v.x));
                    base[2] = f2tf(__uint_as_float(v.y));
                    base[4] = f2tf(__uint_as_float(v.z));
                    base[6] = f2tf(__uint_as_float(v.w));
                }
            }
        }
        __syncthreads();                 // fragments ready

        // MMA loop: per ks, 2 v4 A-loads + 8 v2 B-loads, 16 MMAs.
#pragma unroll
        for (int ks = 0; ks < 4; ++ks) {
            unsigned a[2][4], b[8][2];
#pragma unroll
            for (int mi = 0; mi < 2; ++mi) {
                const int m16 = (wid & 3) * 2 + mi;
                uint4 av = *(const uint4*)&AF[(m16 * 4 + ks) * AGS + lane * 4];
                a[mi][0] = av.x; a[mi][1] = av.y; a[mi][2] = av.z; a[mi][3] = av.w;
            }
#pragma unroll
            for (int nj = 0; nj < 8; ++nj) {
                const int n8 = (wid >> 2) * 8 + nj;
                uint2 bv = *(const uint2*)&BF[(n8 * 4 + ks) * BGS + lane * 2];
                b[nj][0] = bv.x; b[nj][1] = bv.y;
            }
#pragma unroll
            for (int mi = 0; mi < 2; ++mi)
#pragma unroll
                for (int nj = 0; nj < 8; ++nj)
                    mma_tf32(acc[mi][nj], a[mi], b[nj]);
        }
        __syncthreads();                 // mma done before next convert overwrites
    }

    const int wm0 = (wid & 3) * 32;
    const int wn0 = (wid >> 2) * 64;
#pragma unroll
    for (int mi = 0; mi < 2; ++mi) {
#pragma unroll
        for (int nj = 0; nj < 8; ++nj) {
#pragma unroll
            for (int r = 0; r < 4; ++r) {
                const int m = m0 + wm0 + mi * 16 + g + (r >= 2 ? 8 : 0);
                const int n = n0 + wn0 + nj * 8 + 2 * t + (r & 1);
                float v = acc[mi][nj][r] + bias[n];
                if (MODE == 0) {
                    const int which = n >> 10;
                    const int rem   = n & 1023;
                    const int h     = rem >> 6;
                    const int dh    = rem & 63;
                    const int b_    = m >> 11;
                    const int tkn   = m & 2047;
                    float* dst = (which == 0) ? g_Q : (which == 1) ? g_K : g_V;
                    dst[(((size_t)(b_ * HEADS + h) * SEQ) + tkn) * HDIM + dh] = v;
                } else {
                    out[(size_t)m * N + n] = v;
                }
            }
        }
    }
}

// ---------------------------------------------------------------------------
// Flash attention: tf32 mma, fragment-major Q/Kb/Ks/V, cp.async KV pipeline.
// 1 CTA per (bh, 128 q-rows); 8 warps x (16 rows x 64 kv). KV tile 64.
// Smem (words):
//   Qfrag  [8 m16][8 ks][32][4]       8448   (A-frag, pre-scaled tf32)
//   stage x2: raw K 4096 + V 4096    16384
//   Kbfrag / Ksfrag / Vfrag (B-frag)  4224 each
//   P row-major [128][68]             8704
// ---------------------------------------------------------------------------
#define A_QF   0
#define A_STG  (64 * AGS)                   // 8448
#define A_STGW 8192
#define A_KB   (A_STG + 2 * A_STGW)         // 24832
#define A_KS   (A_KB + 64 * BGS)            // 29056
#define A_VF   (A_KS + 64 * BGS)            // 33280
#define A_P    (A_VF + 64 * BGS)            // 37504
#define PLD    68
#define A_WORDS (A_P + 128 * PLD)           // 46208 words = 184832 B
#define NKT (SEQ / 64)                      // 32

__global__ __launch_bounds__(256, 1)
void flash_attn_mma()
{
    extern __shared__ unsigned sma[];
    unsigned* QF = sma + A_QF;
    unsigned* KB = sma + A_KB;
    unsigned* KS = sma + A_KS;
    unsigned* VF = sma + A_VF;
    unsigned* P  = sma + A_P;

    const int bh = blockIdx.y;
    const int q0 = blockIdx.x * 128;
    const float* Qp = g_Q + (size_t)bh * SEQ * HDIM;
    const float* Kp = g_K + (size_t)bh * SEQ * HDIM;
    const float* Vp = g_V + (size_t)bh * SEQ * HDIM;

    const int tid  = threadIdx.x;
    const int wid  = tid >> 5;
    const int lane = tid & 31;
    const int g    = lane >> 2;
    const int t    = lane & 3;
    const int arow = wid * 16;

    // Raw KV stage: K 64x64 (1024 f4) + V 64x64 (1024 f4).
    auto kv_load = [&](int kt, int slot) {
        unsigned* st = sma + A_STG + slot * A_STGW;
#pragma unroll
        for (int i = 0; i < 8; ++i) {
            const int idx = tid + 256 * i;          // 0..2047
            const int f   = idx & 1023;
            const int r   = f >> 4;
            const int c4  = (f & 15) * 4;
            const float* src = ((idx < 1024) ? Kp : Vp)
                               + (size_t)(kt * 64 + r) * HDIM + c4;
            const int off = (idx < 1024) ? (r * 64 + c4) : (4096 + r * 64 + c4);
            CP_ASYNC16(sptr(st + off), src);
        }
    };

    kv_load(0, 0); CP_COMMIT();
    kv_load(1, 1); CP_COMMIT();

    // Prologue: Q -> tf32 A-frag, pre-scaled.
#pragma unroll
    for (int i = 0; i < 8; ++i) {
        const int f = tid + 256 * i;                // 0..2047 f4 over 128x64
        const int r = f >> 4;
        const int c = (f & 15) * 4;
        const int ks = c >> 3, c4 = (c >> 2) & 1;
        float4 q = *(const float4*)&Qp[(size_t)(q0 + r) * HDIM + c];
        const int m16 = r >> 4, hi = (r >> 3) & 1, gg = r & 7;
        unsigned* base = QF + (m16 * 8 + ks) * AGS + gg * 16 + hi + 2 * c4;
        base[0]  = f2tf(q.x * SCALE);
        base[4]  = f2tf(q.y * SCALE);
        base[8]  = f2tf(q.z * SCALE);
        base[12] = f2tf(q.w * SCALE);
    }

    float o[8][4];
    float mrow[2] = {-1e30f, -1e30f};
    float lrow[2] = {0.f, 0.f};
#pragma unroll
    for (int nj = 0; nj < 8; ++nj)
#pragma unroll
        for (int r = 0; r < 4; ++r) o[nj][r] = 0.f;

    const unsigned FULL = 0xffffffffu;

    for (int kt = 0; kt < NKT; ++kt) {
        CP_WAIT1();
        __syncthreads();                // stage kt ready; frags free (prev iter done)

        // Convert pass: K -> Kb,Ks (hi/lo split); V -> Vfrag.
        {
            const unsigned* st = sma + A_STG + (kt & 1) * A_STGW;
#pragma unroll
            for (int i = 0; i < 8; ++i) {
                const int idx = tid + 256 * i;      // 0..2047
                const int f   = idx & 1023;
                const int r   = f >> 4;
                const int c   = (f & 15) * 4;
                if (idx < 1024) {                    // K element [r][c+e]
                    uint4 v = *(const uint4*)&st[r * 64 + c];
                    const int n8 = r >> 3, gg = r & 7;
                    const int ks = c >> 3, c4 = (c >> 2) & 1;
                    const int go = (n8 * 8 + ks) * BGS + gg * 8 + c4;
                    float fv[4] = {__uint_as_float(v.x), __uint_as_float(v.y),
                                   __uint_as_float(v.z), __uint_as_float(v.w)};
#pragma unroll
                    for (int e = 0; e < 4; ++e) {
                        unsigned hi = f2tf(fv[e]);
                        KB[go + e * 2] = hi;
                        KS[go + e * 2] = f2tf(fv[e] - __uint_as_float(hi));
                    }
                } else {                             // V element [r][c+e]: n=c+e, k=r
                    uint4 v = *(const uint4*)&st[4096 + r * 64 + c];
                    const int ks = r >> 3, c4 = (r >> 2) & 1, tt = r & 3;
                    unsigned fv[4] = {v.x, v.y, v.z, v.w};
#pragma unroll
                    for (int e = 0; e < 4; ++e) {
                        const int n = c + e;
                        const int n8 = n >> 3, gg = n & 7;
                        VF[(n8 * 8 + ks) * BGS + (gg * 4 + tt) * 2 + c4] =
                            f2tf(__uint_as_float(fv[e]));
                    }
                }
            }
        }
        __syncthreads();                // fragments ready

        // Prefetch stage kt+2 (stage slot kt&1 fully consumed by convert).
        if (kt + 2 < NKT) kv_load(kt + 2, kt & 1);
        CP_COMMIT();

        // S = Q @ (Kb + Ks)^T
        float s[8][4];
#pragma unroll
        for (int nj = 0; nj < 8; ++nj)
#pragma unroll
            for (int r = 0; r < 4; ++r) s[nj][r] = 0.f;

#pragma unroll
        for (int ks8 = 0; ks8 < 8; ++ks8) {
            unsigned a[4];
            uint4 av = *(const uint4*)&QF[(wid * 8 + ks8) * AGS + lane * 4];
            a[0] = av.x; a[1] = av.y; a[2] = av.z; a[3] = av.w;
#pragma unroll
            for (int nj = 0; nj < 8; ++nj) {
                const int go = (nj * 8 + ks8) * BGS + lane * 2;
                uint2 kb = *(const uint2*)&KB[go];
                uint2 kr = *(const uint2*)&KS[go];
                unsigned bb[2] = {kb.x, kb.y};
                unsigned bs[2] = {kr.x, kr.y};
                mma_tf32(s[nj], a, bb);
                mma_tf32(s[nj], a, bs);
            }
        }

        // Online softmax (rows g and g+8 of warp tile).
#pragma unroll
        for (int h = 0; h < 2; ++h) {
            const int r0 = 2 * h;
            float mx = -1e30f;
#pragma unroll
            for (int nj = 0; nj < 8; ++nj)
                mx = fmaxf(mx, fmaxf(s[nj][r0], s[nj][r0 + 1]));
            mx = fmaxf(mx, __shfl_xor_sync(FULL, mx, 1));
            mx = fmaxf(mx, __shfl_xor_sync(FULL, mx, 2));
            const float mnew = fmaxf(mrow[h], mx);
            const float alpha = __expf(mrow[h] - mnew);
            float rs = 0.f;
#pragma unroll
            for (int nj = 0; nj < 8; ++nj) {
                s[nj][r0]     = __expf(s[nj][r0]     - mnew);
                s[nj][r0 + 1] = __expf(s[nj][r0 + 1] - mnew);
                rs += s[nj][r0] + s[nj][r0 + 1];
            }
            rs += __shfl_xor_sync(FULL, rs, 1);
            rs += __shfl_xor_sync(FULL, rs, 2);
            lrow[h] = alpha * lrow[h] + rs;
            mrow[h] = mnew;
#pragma unroll
            for (int nj = 0; nj < 8; ++nj) {
                o[nj][r0]     *= alpha;
                o[nj][r0 + 1] *= alpha;
            }
        }

        // Stage P (tf32, row-major [128][PLD]); only this warp reads its rows,
        // but sync so V-frag region writes (next iter) can't race anything.
#pragma unroll
        for (int nj = 0; nj < 8; ++nj) {
            uint2 p0 = make_uint2(f2tf(s[nj][0]), f2tf(s[nj][1]));
            *(uint2*)&P[(arow + g) * PLD + nj * 8 + 2 * t] = p0;
            uint2 p1 = make_uint2(f2tf(s[nj][2]), f2tf(s[nj][3]));
            *(uint2*)&P[(arow + g + 8) * PLD + nj * 8 + 2 * t] = p1;
        }
        __syncwarp();                    // P rows are warp-private: warp sync suffices

        // O += P @ V
#pragma unroll
        for (int ks8 = 0; ks8 < 8; ++ks8) {
            const int kk = ks8 * 8;
            unsigned a[4];
            a[0] = P[(arow + g)     * PLD + kk + t];
            a[1] = P[(arow + g + 8) * PLD + kk + t];
            a[2] = P[(arow + g)     * PLD + kk + t + 4];
            a[3] = P[(arow + g + 8) * PLD + kk + t + 4];
#pragma unroll
            for (int nj = 0; nj < 8; ++nj) {
                uint2 bv = *(const uint2*)&VF[(nj * 8 + ks8) * BGS + lane * 2];
                unsigned b[2] = {bv.x, bv.y};
                mma_tf32(o[nj], a, b);
            }
        }
        // Next iteration's top __syncthreads fences frag reuse.
    }

    // Epilogue: normalize, write to g_O [B,N,EMBED].
    const int h  = bh & (HEADS - 1);
    const int b  = bh >> 4;
    const float inv0 = 1.0f / lrow[0];
    const float inv1 = 1.0f / lrow[1];
    const int r0 = q0 + arow + g;
#pragma unroll
    for (int nj = 0; nj < 8; ++nj) {
        const int col = h * HDIM + nj * 8 + 2 * t;
        float2 v0 = make_float2(o[nj][0] * inv0, o[nj][1] * inv0);
        *(float2*)&g_O[(size_t)(b * SEQ + r0) * EMBED + col] = v0;
        float2 v1 = make_float2(o[nj][2] * inv1, o[nj][3] * inv1);
        *(float2*)&g_O[(size_t)(b * SEQ + r0 + 8) * EMBED + col] = v1;
    }
}

// ---------------------------------------------------------------------------
extern "C" void kernel_launch(void* const* d_in, const int* in_sizes, int n_in,
                              void* d_out, int out_size)
{
    const float* x      = (const float*)d_in[0];
    const float* w_qkv  = (const float*)d_in[1];
    const float* b_qkv  = (const float*)d_in[2];
    const float* w_proj = (const float*)d_in[3];
    const float* b_proj = (const float*)d_in[4];
    float* out = (float*)d_out;

    float* gO = nullptr;
    cudaGetSymbolAddress((void**)&gO, g_O);

    static bool attr_set = false;
    if (!attr_set) {
        cudaFuncSetAttribute(gemm_mma<0>,
                             cudaFuncAttributeMaxDynamicSharedMemorySize, G_WORDS * 4);
        cudaFuncSetAttribute(gemm_mma<1>,
                             cudaFuncAttributeMaxDynamicSharedMemorySize, G_WORDS * 4);
        cudaFuncSetAttribute(flash_attn_mma,
                             cudaFuncAttributeMaxDynamicSharedMemorySize, A_WORDS * 4);
        attr_set = true;
    }

    // 1) QKV projection
    {
        dim3 grid(QKVN / 128, MTOK / 128);
        gemm_mma<0><<<grid, 256, G_WORDS * 4>>>(x, w_qkv, b_qkv, nullptr, MTOK, QKVN, EMBED);
    }
    // 2) Flash attention -> g_O
    {
        dim3 grid(SEQ / 128, BATCH * HEADS);
        flash_attn_mma<<<grid, 256, A_WORDS * 4>>>();
    }
    // 3) Output projection
    {
        dim3 grid(EMBED / 128, MTOK / 128);
        gemm_mma<1><<<grid, 256, G_WORDS * 4>>>(gO, w_proj, b_proj, out, MTOK, EMBED, EMBED);
    }
}

// round 9
// speedup vs baseline: 1.2212x; 1.1454x over previous
#include <cuda_runtime.h>

// ---------------------------------------------------------------------------
// Fused MHA block (mma.sync only — tcgen05 unavailable at .target sm_100):
//   QKV GEMM  : tf32 m16n8k8 (Round-3 proven)
//   attention : S via bf16 m16n8k16 3-term split + ldmatrix; PV via tf32
//   proj GEMM : tf32 m16n8k8 (Round-3 proven)
// Shapes: B=2, N=2048, EMBED=1024, HEADS=16, HDIM=64.
// ---------------------------------------------------------------------------

#define BATCH  2
#define SEQ    2048
#define EMBED  1024
#define HEADS  16
#define HDIM   64
#define MTOK   (BATCH * SEQ)      // 4096
#define QKVN   (3 * EMBED)        // 3072
#define SCALE  0.125f             // HDIM^-0.5

__device__ float g_Q[BATCH * HEADS * SEQ * HDIM];   // [B,H,N,Dh]
__device__ float g_K[BATCH * HEADS * SEQ * HDIM];
__device__ float g_V[BATCH * HEADS * SEQ * HDIM];
__device__ float g_O[BATCH * SEQ * EMBED];          // attention output [B,N,EMBED]

// ------------------------------- helpers -----------------------------------
__device__ __forceinline__ unsigned f2tf(float f) {
    unsigned r;
    asm("cvt.rna.tf32.f32 %0, %1;" : "=r"(r) : "f"(f));
    return r;
}
__device__ __forceinline__ unsigned short f2bf(float f) {
    unsigned short u;
    asm("cvt.rn.bf16.f32 %0, %1;" : "=h"(u) : "f"(f));
    return u;
}
__device__ __forceinline__ float bf2f(unsigned short u) {
    return __uint_as_float(((unsigned)u) << 16);
}
__device__ __forceinline__ void mma_tf32(float* c, const unsigned* a, const unsigned* b) {
    asm volatile(
        "mma.sync.aligned.m16n8k8.row.col.f32.tf32.tf32.f32 "
        "{%0,%1,%2,%3}, {%4,%5,%6,%7}, {%8,%9}, {%0,%1,%2,%3};\n"
        : "+f"(c[0]), "+f"(c[1]), "+f"(c[2]), "+f"(c[3])
        : "r"(a[0]), "r"(a[1]), "r"(a[2]), "r"(a[3]),
          "r"(b[0]), "r"(b[1]));
}
__device__ __forceinline__ void mma_bf16(float* c, const unsigned* a, const unsigned* b) {
    asm volatile(
        "mma.sync.aligned.m16n8k16.row.col.f32.bf16.bf16.f32 "
        "{%0,%1,%2,%3}, {%4,%5,%6,%7}, {%8,%9}, {%0,%1,%2,%3};\n"
        : "+f"(c[0]), "+f"(c[1]), "+f"(c[2]), "+f"(c[3])
        : "r"(a[0]), "r"(a[1]), "r"(a[2]), "r"(a[3]),
          "r"(b[0]), "r"(b[1]));
}
__device__ __forceinline__ void ldsm_x4(unsigned& r0, unsigned& r1,
                                        unsigned& r2, unsigned& r3, unsigned addr) {
    asm volatile("ldmatrix.sync.aligned.m8n8.x4.shared.b16 {%0,%1,%2,%3}, [%4];"
                 : "=r"(r0), "=r"(r1), "=r"(r2), "=r"(r3) : "r"(addr));
}
__device__ __forceinline__ unsigned smem_u32(const void* p) {
    return (unsigned)__cvta_generic_to_shared(p);
}

// ---------------------------------------------------------------------------
// GEMM: C[M,N] = A[M,K] @ W[N,K]^T + bias[N]  (tf32 mma.sync, Round-3 proven)
// ---------------------------------------------------------------------------
template <int MODE>
__global__ __launch_bounds__(256)
void gemm_mma(const float* __restrict__ A, const float* __restrict__ W,
              const float* __restrict__ bias, float* __restrict__ out,
              int M, int N, int K)
{
    constexpr int BM = 128, BN = 128, BK = 32;
    constexpr int LDT = BK + 4;
    __shared__ unsigned As[BM * LDT];
    __shared__ unsigned Bs[BN * LDT];

    const int tid  = threadIdx.x;
    const int wid  = tid >> 5;
    const int lane = tid & 31;
    const int g    = lane >> 2;
    const int t    = lane & 3;

    const int wm0 = (wid & 3) * 32;
    const int wn0 = (wid >> 2) * 64;

    const int m0 = blockIdx.y * BM;
    const int n0 = blockIdx.x * BN;

    float acc[2][8][4];
#pragma unroll
    for (int mi = 0; mi < 2; ++mi)
#pragma unroll
        for (int nj = 0; nj < 8; ++nj)
#pragma unroll
            for (int r = 0; r < 4; ++r) acc[mi][nj][r] = 0.f;

    const int srow = tid >> 3;
    const int scol = (tid & 7) * 4;

    for (int k0 = 0; k0 < K; k0 += BK) {
#pragma unroll
        for (int r = 0; r < 4; ++r) {
            const int row = srow + 32 * r;
            float4 a = *(const float4*)&A[(size_t)(m0 + row) * K + k0 + scol];
            uint4 at = make_uint4(f2tf(a.x), f2tf(a.y), f2tf(a.z), f2tf(a.w));
            *(uint4*)&As[row * LDT + scol] = at;
            float4 b = *(const float4*)&W[(size_t)(n0 + row) * K + k0 + scol];
            uint4 bt = make_uint4(f2tf(b.x), f2tf(b.y), f2tf(b.z), f2tf(b.w));
            *(uint4*)&Bs[row * LDT + scol] = bt;
        }
        __syncthreads();

#pragma unroll
        for (int ks = 0; ks < BK / 8; ++ks) {
            const int kk = ks * 8;
            unsigned a[2][4], b[8][2];
#pragma unroll
            for (int mi = 0; mi < 2; ++mi) {
                const int mb = wm0 + mi * 16;
                a[mi][0] = As[(mb + g)     * LDT + kk + t];
                a[mi][1] = As[(mb + g + 8) * LDT + kk + t];
                a[mi][2] = As[(mb + g)     * LDT + kk + t + 4];
                a[mi][3] = As[(mb + g + 8) * LDT + kk + t + 4];
            }
#pragma unroll
            for (int nj = 0; nj < 8; ++nj) {
                const int nb = wn0 + nj * 8 + g;
                b[nj][0] = Bs[nb * LDT + kk + t];
                b[nj][1] = Bs[nb * LDT + kk + t + 4];
            }
#pragma unroll
            for (int mi = 0; mi < 2; ++mi)
#pragma unroll
                for (int nj = 0; nj < 8; ++nj)
                    mma_tf32(acc[mi][nj], a[mi], b[nj]);
        }
        __syncthreads();
    }

#pragma unroll
    for (int mi = 0; mi < 2; ++mi) {
#pragma unroll
        for (int nj = 0; nj < 8; ++nj) {
#pragma unroll
            for (int r = 0; r < 4; ++r) {
                const int m = m0 + wm0 + mi * 16 + g + (r >= 2 ? 8 : 0);
                const int n = n0 + wn0 + nj * 8 + 2 * t + (r & 1);
                float v = acc[mi][nj][r] + bias[n];
                if (MODE == 0) {
                    const int which = n >> 10;
                    const int rem   = n & 1023;
                    const int h     = rem >> 6;
                    const int dh    = rem & 63;
                    const int b_    = m >> 11;
                    const int tkn   = m & 2047;
                    float* dst = (which == 0) ? g_Q : (which == 1) ? g_K : g_V;
                    dst[(((size_t)(b_ * HEADS + h) * SEQ) + tkn) * HDIM + dh] = v;
                } else {
                    out[(size_t)m * N + n] = v;
                }
            }
        }
    }
}

// ---------------------------------------------------------------------------
// Flash attention: S on bf16 m16n8k16 (3-term split, ldmatrix), PV on tf32.
// 1 CTA per (bh, 128 q-rows); 8 warps x (16 q-rows x 64 kv). KV tile 64.
// Smem (bytes), bf16 tiles use 144B row stride (36 words: conflict-free LDSM):
//   QH [128][72b16] 18432 | QL 18432 | KH [64][72] 9216 | KL 9216
//   V tf32 [64][68w] 17408 | P tf32 [128][68w] 34816      total 107520
// ---------------------------------------------------------------------------
#define AQH 0
#define AQL 18432
#define AKH 36864
#define AKL 46080
#define AVV 55296
#define APP 72704
#define SM_BYTES 107520
#define VLD 68
#define PLD 68

__global__ __launch_bounds__(256, 2)
void flash_attn_mma()
{
    extern __shared__ char smc[];
    const unsigned sbase = smem_u32(smc);
    unsigned* Vs = (unsigned*)(smc + AVV);
    unsigned* P  = (unsigned*)(smc + APP);

    const int bh = blockIdx.y;
    const int q0 = blockIdx.x * 128;
    const float* Qp = g_Q + (size_t)bh * SEQ * HDIM;
    const float* Kp = g_K + (size_t)bh * SEQ * HDIM;
    const float* Vp = g_V + (size_t)bh * SEQ * HDIM;

    const int tid  = threadIdx.x;
    const int wid  = tid >> 5;
    const int lane = tid & 31;
    const int g    = lane >> 2;
    const int t    = lane & 3;
    const int arow = wid * 16;

    // Prologue: Q -> bf16 hi/lo tiles, pre-scaled.
#pragma unroll
    for (int it = 0; it < 8; ++it) {
        const int idx = tid + 256 * it;      // 0..2047 over 128x16 f4
        const int r = idx >> 4;
        const int c = (idx & 15) * 4;
        float4 q = *(const float4*)&Qp[(size_t)(q0 + r) * HDIM + c];
        float f[4] = {q.x * SCALE, q.y * SCALE, q.z * SCALE, q.w * SCALE};
        unsigned short h[4], l[4];
#pragma unroll
        for (int e = 0; e < 4; ++e) {
            h[e] = f2bf(f[e]);
            l[e] = f2bf(f[e] - bf2f(h[e]));
        }
        const int bo = r * 144 + c * 2;      // 8B aligned
        *(uint2*)(smc + AQH + bo) = make_uint2((unsigned)h[0] | ((unsigned)h[1] << 16),
                                               (unsigned)h[2] | ((unsigned)h[3] << 16));
        *(uint2*)(smc + AQL + bo) = make_uint2((unsigned)l[0] | ((unsigned)l[1] << 16),
                                               (unsigned)l[2] | ((unsigned)l[3] << 16));
    }

    float o[8][4];
    float mrow[2] = {-1e30f, -1e30f};
    float lrow[2] = {0.f, 0.f};
#pragma unroll
    for (int nj = 0; nj < 8; ++nj)
#pragma unroll
        for (int r = 0; r < 4; ++r) o[nj][r] = 0.f;

    const unsigned FULL = 0xffffffffu;

    // ldmatrix lane address components (byte offsets within a tile).
    const int q_row = arow + (lane & 15);
    const int q_koф = ((lane >> 4) << 3);
    const int b_rsub = ((lane >> 4) << 3) + (lane & 7);
    const int b_koф = (((lane >> 3) & 1) << 3);

    for (int kt = 0; kt < SEQ / 64; ++kt) {
        __syncthreads();   // prior PV reads of Vs done; K/L tiles free
        // Stage K -> bf16 hi/lo, V -> tf32.
#pragma unroll
        for (int it = 0; it < 4; ++it) {
            const int idx = tid + 256 * it;  // 0..1023 over 64x16 f4
            const int r = idx >> 4;
            const int c = (idx & 15) * 4;
            float4 kk = *(const float4*)&Kp[(size_t)(kt * 64 + r) * HDIM + c];
            float f[4] = {kk.x, kk.y, kk.z, kk.w};
            unsigned short h[4], l[4];
#pragma unroll
            for (int e = 0; e < 4; ++e) {
                h[e] = f2bf(f[e]);
                l[e] = f2bf(f[e] - bf2f(h[e]));
            }
            const int bo = r * 144 + c * 2;
            *(uint2*)(smc + AKH + bo) = make_uint2((unsigned)h[0] | ((unsigned)h[1] << 16),
                                                   (unsigned)h[2] | ((unsigned)h[3] << 16));
            *(uint2*)(smc + AKL + bo) = make_uint2((unsigned)l[0] | ((unsigned)l[1] << 16),
                                                   (unsigned)l[2] | ((unsigned)l[3] << 16));
            float4 vv = *(const float4*)&Vp[(size_t)(kt * 64 + r) * HDIM + c];
            Vs[r * VLD + c + 0] = f2tf(vv.x);
            Vs[r * VLD + c + 1] = f2tf(vv.y);
            Vs[r * VLD + c + 2] = f2tf(vv.z);
            Vs[r * VLD + c + 3] = f2tf(vv.w);
        }
        __syncthreads();

        // S = (Qh+Ql) @ (Kh+Kl)^T, 3-term bf16: QhKh + QhKl + QlKh.
        float s[8][4];
#pragma unroll
        for (int nj = 0; nj < 8; ++nj)
#pragma unroll
            for (int r = 0; r < 4; ++r) s[nj][r] = 0.f;

#pragma unroll
        for (int c16 = 0; c16 < 4; ++c16) {
            const unsigned qoff = (unsigned)(q_row * 144 + (c16 * 16 + q_koф) * 2);
            unsigned ah[4], al[4];
            ldsm_x4(ah[0], ah[1], ah[2], ah[3], sbase + AQH + qoff);
            ldsm_x4(al[0], al[1], al[2], al[3], sbase + AQL + qoff);
#pragma unroll
            for (int njp = 0; njp < 4; ++njp) {
                const unsigned boff = (unsigned)((njp * 16 + b_rsub) * 144
                                                 + (c16 * 16 + b_koф) * 2);
                unsigned bhv[4], blv[4];
                ldsm_x4(bhv[0], bhv[1], bhv[2], bhv[3], sbase + AKH + boff);
                ldsm_x4(blv[0], blv[1], blv[2], blv[3], sbase + AKL + boff);
                mma_bf16(s[2 * njp],     ah, bhv + 0);
                mma_bf16(s[2 * njp],     ah, blv + 0);
                mma_bf16(s[2 * njp],     al, bhv + 0);
                mma_bf16(s[2 * njp + 1], ah, bhv + 2);
                mma_bf16(s[2 * njp + 1], ah, blv + 2);
                mma_bf16(s[2 * njp + 1], al, bhv + 2);
            }
        }

        // Online softmax (rows g and g+8 of warp tile).
#pragma unroll
        for (int h = 0; h < 2; ++h) {
            const int r0 = 2 * h;
            float mx = -1e30f;
#pragma unroll
            for (int nj = 0; nj < 8; ++nj)
                mx = fmaxf(mx, fmaxf(s[nj][r0], s[nj][r0 + 1]));
            mx = fmaxf(mx, __shfl_xor_sync(FULL, mx, 1));
            mx = fmaxf(mx, __shfl_xor_sync(FULL, mx, 2));
            const float mnew = fmaxf(mrow[h], mx);
            const float alpha = __expf(mrow[h] - mnew);
            float rs = 0.f;
#pragma unroll
            for (int nj = 0; nj < 8; ++nj) {
                s[nj][r0]     = __expf(s[nj][r0]     - mnew);
                s[nj][r0 + 1] = __expf(s[nj][r0 + 1] - mnew);
                rs += s[nj][r0] + s[nj][r0 + 1];
            }
            rs += __shfl_xor_sync(FULL, rs, 1);
            rs += __shfl_xor_sync(FULL, rs, 2);
            lrow[h] = alpha * lrow[h] + rs;
            mrow[h] = mnew;
#pragma unroll
            for (int nj = 0; nj < 8; ++nj) {
                o[nj][r0]     *= alpha;
                o[nj][r0 + 1] *= alpha;
            }
        }

        // Stage P (tf32, warp-private rows).
#pragma unroll
        for (int nj = 0; nj < 8; ++nj) {
            uint2 p0 = make_uint2(f2tf(s[nj][0]), f2tf(s[nj][1]));
            *(uint2*)&P[(arow + g) * PLD + nj * 8 + 2 * t] = p0;
            uint2 p1 = make_uint2(f2tf(s[nj][2]), f2tf(s[nj][3]));
            *(uint2*)&P[(arow + g + 8) * PLD + nj * 8 + 2 * t] = p1;
        }
        __syncwarp();

        // O += P @ V (tf32).
#pragma unroll
        for (int ks8 = 0; ks8 < 8; ++ks8) {
            const int kk = ks8 * 8;
            unsigned a[4];
            a[0] = P[(arow + g)     * PLD + kk + t];
            a[1] = P[(arow + g + 8) * PLD + kk + t];
            a[2] = P[(arow + g)     * PLD + kk + t + 4];
            a[3] = P[(arow + g + 8) * PLD + kk + t + 4];
#pragma unroll
            for (int nj = 0; nj < 8; ++nj) {
                unsigned b[2];
                b[0] = Vs[(kk + t)     * VLD + nj * 8 + g];
                b[1] = Vs[(kk + t + 4) * VLD + nj * 8 + g];
                mma_tf32(o[nj], a, b);
            }
        }
    }

    // Epilogue: normalize, write to g_O [B,N,EMBED].
    const int h  = bh & (HEADS - 1);
    const int b  = bh >> 4;
    const float inv0 = 1.0f / lrow[0];
    const float inv1 = 1.0f / lrow[1];
    const int r0 = q0 + arow + g;
#pragma unroll
    for (int nj = 0; nj < 8; ++nj) {
        const int col = h * HDIM + nj * 8 + 2 * t;
        float2 v0 = make_float2(o[nj][0] * inv0, o[nj][1] * inv0);
        *(float2*)&g_O[(size_t)(b * SEQ + r0) * EMBED + col] = v0;
        float2 v1 = make_float2(o[nj][2] * inv1, o[nj][3] * inv1);
        *(float2*)&g_O[(size_t)(b * SEQ + r0 + 8) * EMBED + col] = v1;
    }
}

// ---------------------------------------------------------------------------
extern "C" void kernel_launch(void* const* d_in, const int* in_sizes, int n_in,
                              void* d_out, int out_size)
{
    const float* x      = (const float*)d_in[0];
    const float* w_qkv  = (const float*)d_in[1];
    const float* b_qkv  = (const float*)d_in[2];
    const float* w_proj = (const float*)d_in[3];
    const float* b_proj = (const float*)d_in[4];
    float* out = (float*)d_out;

    float* gO = nullptr;
    cudaGetSymbolAddress((void**)&gO, g_O);

    static bool attr_set = false;
    if (!attr_set) {
        cudaFuncSetAttribute(flash_attn_mma,
                             cudaFuncAttributeMaxDynamicSharedMemorySize, SM_BYTES);
        attr_set = true;
    }

    // 1) QKV projection (tf32 mma) -> g_Q/g_K/g_V
    {
        dim3 grid(QKVN / 128, MTOK / 128);
        gemm_mma<0><<<grid, 256>>>(x, w_qkv, b_qkv, nullptr, MTOK, QKVN, EMBED);
    }
    // 2) Flash attention (bf16-split S + tf32 PV) -> g_O
    {
        dim3 grid(SEQ / 128, BATCH * HEADS);
        flash_attn_mma<<<grid, 256, SM_BYTES>>>();
    }
    // 3) Output projection (tf32 mma)
    {
        dim3 grid(EMBED / 128, MTOK / 128);
        gemm_mma<1><<<grid, 256>>>(gO, w_proj, b_proj, out, MTOK, EMBED, EMBED);
    }
}

// round 10
// speedup vs baseline: 1.3992x; 1.1458x over previous
#include <cuda_runtime.h>

// ---------------------------------------------------------------------------
// Fused MHA block (mma.sync only — tcgen05 unavailable at .target sm_100):
//   QKV GEMM  : tf32 m16n8k8 (proven)
//   attention : S bf16 m16n8k16 3-term + ldmatrix; PV bf16 3-term with
//               P built in registers from S fragments (no smem round trip)
//   proj GEMM : tf32 m16n8k8 (proven)
// Shapes: B=2, N=2048, EMBED=1024, HEADS=16, HDIM=64.
// ---------------------------------------------------------------------------

#define BATCH  2
#define SEQ    2048
#define EMBED  1024
#define HEADS  16
#define HDIM   64
#define MTOK   (BATCH * SEQ)      // 4096
#define QKVN   (3 * EMBED)        // 3072
#define SCALE  0.125f             // HDIM^-0.5

__device__ float g_Q[BATCH * HEADS * SEQ * HDIM];   // [B,H,N,Dh]
__device__ float g_K[BATCH * HEADS * SEQ * HDIM];
__device__ float g_V[BATCH * HEADS * SEQ * HDIM];
__device__ float g_O[BATCH * SEQ * EMBED];          // attention output [B,N,EMBED]

// ------------------------------- helpers -----------------------------------
__device__ __forceinline__ unsigned f2tf(float f) {
    unsigned r;
    asm("cvt.rna.tf32.f32 %0, %1;" : "=r"(r) : "f"(f));
    return r;
}
// Pack two floats into bf16x2: f0 -> low half, f1 -> high half.
__device__ __forceinline__ unsigned pk_bf(float f0, float f1) {
    unsigned d;
    asm("cvt.rn.bf16x2.f32 %0, %1, %2;" : "=r"(d) : "f"(f1), "f"(f0));
    return d;
}
// Split a float pair into bf16 hi-pair + residual lo-pair.
__device__ __forceinline__ void bfsplit2(float f0, float f1, unsigned& hi, unsigned& lo) {
    hi = pk_bf(f0, f1);
    float e0 = __uint_as_float(hi << 16);
    float e1 = __uint_as_float(hi & 0xffff0000u);
    lo = pk_bf(f0 - e0, f1 - e1);
}
__device__ __forceinline__ void mma_tf32(float* c, const unsigned* a, const unsigned* b) {
    asm volatile(
        "mma.sync.aligned.m16n8k8.row.col.f32.tf32.tf32.f32 "
        "{%0,%1,%2,%3}, {%4,%5,%6,%7}, {%8,%9}, {%0,%1,%2,%3};\n"
        : "+f"(c[0]), "+f"(c[1]), "+f"(c[2]), "+f"(c[3])
        : "r"(a[0]), "r"(a[1]), "r"(a[2]), "r"(a[3]),
          "r"(b[0]), "r"(b[1]));
}
__device__ __forceinline__ void mma_bf16(float* c, const unsigned* a, const unsigned* b) {
    asm volatile(
        "mma.sync.aligned.m16n8k16.row.col.f32.bf16.bf16.f32 "
        "{%0,%1,%2,%3}, {%4,%5,%6,%7}, {%8,%9}, {%0,%1,%2,%3};\n"
        : "+f"(c[0]), "+f"(c[1]), "+f"(c[2]), "+f"(c[3])
        : "r"(a[0]), "r"(a[1]), "r"(a[2]), "r"(a[3]),
          "r"(b[0]), "r"(b[1]));
}
__device__ __forceinline__ void ldsm_x4(unsigned& r0, unsigned& r1,
                                        unsigned& r2, unsigned& r3, unsigned addr) {
    asm volatile("ldmatrix.sync.aligned.m8n8.x4.shared.b16 {%0,%1,%2,%3}, [%4];"
                 : "=r"(r0), "=r"(r1), "=r"(r2), "=r"(r3) : "r"(addr));
}
__device__ __forceinline__ void ldsm_x4t(unsigned& r0, unsigned& r1,
                                         unsigned& r2, unsigned& r3, unsigned addr) {
    asm volatile("ldmatrix.sync.aligned.m8n8.x4.trans.shared.b16 {%0,%1,%2,%3}, [%4];"
                 : "=r"(r0), "=r"(r1), "=r"(r2), "=r"(r3) : "r"(addr));
}
__device__ __forceinline__ unsigned smem_u32(const void* p) {
    return (unsigned)__cvta_generic_to_shared(p);
}

// ---------------------------------------------------------------------------
// GEMM: C[M,N] = A[M,K] @ W[N,K]^T + bias[N]  (tf32 mma.sync, proven)
// ---------------------------------------------------------------------------
template <int MODE>
__global__ __launch_bounds__(256)
void gemm_mma(const float* __restrict__ A, const float* __restrict__ W,
              const float* __restrict__ bias, float* __restrict__ out,
              int M, int N, int K)
{
    constexpr int BM = 128, BN = 128, BK = 32;
    constexpr int LDT = BK + 4;
    __shared__ unsigned As[BM * LDT];
    __shared__ unsigned Bs[BN * LDT];

    const int tid  = threadIdx.x;
    const int wid  = tid >> 5;
    const int lane = tid & 31;
    const int g    = lane >> 2;
    const int t    = lane & 3;

    const int wm0 = (wid & 3) * 32;
    const int wn0 = (wid >> 2) * 64;

    const int m0 = blockIdx.y * BM;
    const int n0 = blockIdx.x * BN;

    float acc[2][8][4];
#pragma unroll
    for (int mi = 0; mi < 2; ++mi)
#pragma unroll
        for (int nj = 0; nj < 8; ++nj)
#pragma unroll
            for (int r = 0; r < 4; ++r) acc[mi][nj][r] = 0.f;

    const int srow = tid >> 3;
    const int scol = (tid & 7) * 4;

    for (int k0 = 0; k0 < K; k0 += BK) {
#pragma unroll
        for (int r = 0; r < 4; ++r) {
            const int row = srow + 32 * r;
            float4 a = *(const float4*)&A[(size_t)(m0 + row) * K + k0 + scol];
            uint4 at = make_uint4(f2tf(a.x), f2tf(a.y), f2tf(a.z), f2tf(a.w));
            *(uint4*)&As[row * LDT + scol] = at;
            float4 b = *(const float4*)&W[(size_t)(n0 + row) * K + k0 + scol];
            uint4 bt = make_uint4(f2tf(b.x), f2tf(b.y), f2tf(b.z), f2tf(b.w));
            *(uint4*)&Bs[row * LDT + scol] = bt;
        }
        __syncthreads();

#pragma unroll
        for (int ks = 0; ks < BK / 8; ++ks) {
            const int kk = ks * 8;
            unsigned a[2][4], b[8][2];
#pragma unroll
            for (int mi = 0; mi < 2; ++mi) {
                const int mb = wm0 + mi * 16;
                a[mi][0] = As[(mb + g)     * LDT + kk + t];
                a[mi][1] = As[(mb + g + 8) * LDT + kk + t];
                a[mi][2] = As[(mb + g)     * LDT + kk + t + 4];
                a[mi][3] = As[(mb + g + 8) * LDT + kk + t + 4];
            }
#pragma unroll
            for (int nj = 0; nj < 8; ++nj) {
                const int nb = wn0 + nj * 8 + g;
                b[nj][0] = Bs[nb * LDT + kk + t];
                b[nj][1] = Bs[nb * LDT + kk + t + 4];
            }
#pragma unroll
            for (int mi = 0; mi < 2; ++mi)
#pragma unroll
                for (int nj = 0; nj < 8; ++nj)
                    mma_tf32(acc[mi][nj], a[mi], b[nj]);
        }
        __syncthreads();
    }

#pragma unroll
    for (int mi = 0; mi < 2; ++mi) {
#pragma unroll
        for (int nj = 0; nj < 8; ++nj) {
#pragma unroll
            for (int r = 0; r < 4; ++r) {
                const int m = m0 + wm0 + mi * 16 + g + (r >= 2 ? 8 : 0);
                const int n = n0 + wn0 + nj * 8 + 2 * t + (r & 1);
                float v = acc[mi][nj][r] + bias[n];
                if (MODE == 0) {
                    const int which = n >> 10;
                    const int rem   = n & 1023;
                    const int h     = rem >> 6;
                    const int dh    = rem & 63;
                    const int b_    = m >> 11;
                    const int tkn   = m & 2047;
                    float* dst = (which == 0) ? g_Q : (which == 1) ? g_K : g_V;
                    dst[(((size_t)(b_ * HEADS + h) * SEQ) + tkn) * HDIM + dh] = v;
                } else {
                    out[(size_t)m * N + n] = v;
                }
            }
        }
    }
}

// ---------------------------------------------------------------------------
// Flash attention: S and PV both on bf16 m16n8k16 3-term split.
// 1 CTA per (bh, 128 q-rows); 8 warps x (16 q-rows x 64 kv). KV tile 64.
// Smem (bytes), all bf16 tiles 144B row stride (36 words, conflict-free LDSM):
//   QH [128][72] 18432 | QL 18432 | KH [64][72] 9216 | KL 9216
//   VH [64][72]   9216 | VL  9216                       total 73728
// ---------------------------------------------------------------------------
#define AQH 0
#define AQL 18432
#define AKH 36864
#define AKL 46080
#define AVH 55296
#define AVL 64512
#define SM_BYTES 73728

__global__ __launch_bounds__(256, 2)
void flash_attn_mma()
{
    extern __shared__ char smc[];
    const unsigned sbase = smem_u32(smc);

    const int bh = blockIdx.y;
    const int q0 = blockIdx.x * 128;
    const float* Qp = g_Q + (size_t)bh * SEQ * HDIM;
    const float* Kp = g_K + (size_t)bh * SEQ * HDIM;
    const float* Vp = g_V + (size_t)bh * SEQ * HDIM;

    const int tid  = threadIdx.x;
    const int wid  = tid >> 5;
    const int lane = tid & 31;
    const int g    = lane >> 2;
    const int t    = lane & 3;
    const int arow = wid * 16;

    // Prologue: Q -> bf16 hi/lo tiles, pre-scaled.
#pragma unroll
    for (int it = 0; it < 8; ++it) {
        const int idx = tid + 256 * it;      // 0..2047 over 128x16 f4
        const int r = idx >> 4;
        const int c = (idx & 15) * 4;
        float4 q = *(const float4*)&Qp[(size_t)(q0 + r) * HDIM + c];
        unsigned h01, l01, h23, l23;
        bfsplit2(q.x * SCALE, q.y * SCALE, h01, l01);
        bfsplit2(q.z * SCALE, q.w * SCALE, h23, l23);
        const int bo = r * 144 + c * 2;
        *(uint2*)(smc + AQH + bo) = make_uint2(h01, h23);
        *(uint2*)(smc + AQL + bo) = make_uint2(l01, l23);
    }

    float o[8][4];
    float mrow[2] = {-1e30f, -1e30f};
    float lrow[2] = {0.f, 0.f};
#pragma unroll
    for (int nj = 0; nj < 8; ++nj)
#pragma unroll
        for (int r = 0; r < 4; ++r) o[nj][r] = 0.f;

    const unsigned FULL = 0xffffffffu;

    // ldmatrix lane address components.
    const int q_row = arow + (lane & 15);           // A-frag rows (Q and P)
    const int q_ko  = (lane >> 4) << 3;             // A-frag k-offset
    const int b_rs  = ((lane >> 4) << 3) + (lane & 7);   // K B-frag row
    const int b_ko  = ((lane >> 3) & 1) << 3;            // K B-frag k-offset
    const int v_row = (((lane >> 3) & 1) << 3) + (lane & 7); // V trans row (kv)
    const int v_co  = (lane >> 4) << 3;                      // V trans dh-offset

    for (int kt = 0; kt < SEQ / 64; ++kt) {
        __syncthreads();   // prior S/PV ldsm reads done; tiles free
        // Stage K -> bf16 hi/lo, V -> bf16 hi/lo.
#pragma unroll
        for (int it = 0; it < 4; ++it) {
            const int idx = tid + 256 * it;  // 0..1023 over 64x16 f4
            const int r = idx >> 4;
            const int c = (idx & 15) * 4;
            const int bo = r * 144 + c * 2;
            float4 kk = *(const float4*)&Kp[(size_t)(kt * 64 + r) * HDIM + c];
            unsigned h01, l01, h23, l23;
            bfsplit2(kk.x, kk.y, h01, l01);
            bfsplit2(kk.z, kk.w, h23, l23);
            *(uint2*)(smc + AKH + bo) = make_uint2(h01, h23);
            *(uint2*)(smc + AKL + bo) = make_uint2(l01, l23);
            float4 vv = *(const float4*)&Vp[(size_t)(kt * 64 + r) * HDIM + c];
            bfsplit2(vv.x, vv.y, h01, l01);
            bfsplit2(vv.z, vv.w, h23, l23);
            *(uint2*)(smc + AVH + bo) = make_uint2(h01, h23);
            *(uint2*)(smc + AVL + bo) = make_uint2(l01, l23);
        }
        __syncthreads();

        // S = (Qh+Ql) @ (Kh+Kl)^T : QhKh + QhKl + QlKh.
        float s[8][4];
#pragma unroll
        for (int nj = 0; nj < 8; ++nj)
#pragma unroll
            for (int r = 0; r < 4; ++r) s[nj][r] = 0.f;

#pragma unroll
        for (int c16 = 0; c16 < 4; ++c16) {
            const unsigned qoff = (unsigned)(q_row * 144 + (c16 * 16 + q_ko) * 2);
            unsigned ah[4], al[4];
            ldsm_x4(ah[0], ah[1], ah[2], ah[3], sbase + AQH + qoff);
            ldsm_x4(al[0], al[1], al[2], al[3], sbase + AQL + qoff);
#pragma unroll
            for (int njp = 0; njp < 4; ++njp) {
                const unsigned boff = (unsigned)((njp * 16 + b_rs) * 144
                                                 + (c16 * 16 + b_ko) * 2);
                unsigned bhv[4], blv[4];
                ldsm_x4(bhv[0], bhv[1], bhv[2], bhv[3], sbase + AKH + boff);
                ldsm_x4(blv[0], blv[1], blv[2], blv[3], sbase + AKL + boff);
                mma_bf16(s[2 * njp],     ah, bhv + 0);
                mma_bf16(s[2 * njp],     ah, blv + 0);
                mma_bf16(s[2 * njp],     al, bhv + 0);
                mma_bf16(s[2 * njp + 1], ah, bhv + 2);
                mma_bf16(s[2 * njp + 1], ah, blv + 2);
                mma_bf16(s[2 * njp + 1], al, bhv + 2);
            }
        }

        // Online softmax (rows g and g+8 of warp tile).
#pragma unroll
        for (int h = 0; h < 2; ++h) {
            const int r0 = 2 * h;
            float mx = -1e30f;
#pragma unroll
            for (int nj = 0; nj < 8; ++nj)
                mx = fmaxf(mx, fmaxf(s[nj][r0], s[nj][r0 + 1]));
            mx = fmaxf(mx, __shfl_xor_sync(FULL, mx, 1));
            mx = fmaxf(mx, __shfl_xor_sync(FULL, mx, 2));
            const float mnew = fmaxf(mrow[h], mx);
            const float alpha = __expf(mrow[h] - mnew);
            float rs = 0.f;
#pragma unroll
            for (int nj = 0; nj < 8; ++nj) {
                s[nj][r0]     = __expf(s[nj][r0]     - mnew);
                s[nj][r0 + 1] = __expf(s[nj][r0 + 1] - mnew);
                rs += s[nj][r0] + s[nj][r0 + 1];
            }
            rs += __shfl_xor_sync(FULL, rs, 1);
            rs += __shfl_xor_sync(FULL, rs, 2);
            lrow[h] = alpha * lrow[h] + rs;
            mrow[h] = mnew;
#pragma unroll
            for (int nj = 0; nj < 8; ++nj) {
                o[nj][r0]     *= alpha;
                o[nj][r0 + 1] *= alpha;
            }
        }

        // O += P @ V. P's A-fragments come straight from the S fragments:
        // a0=(g,k2t)=s[2c16][0,1]  a1=(g+8)=s[2c16][2,3]
        // a2=(g,k+8)=s[2c16+1][0,1] a3=s[2c16+1][2,3]   (bf16 hi/lo split)
#pragma unroll
        for (int c16 = 0; c16 < 4; ++c16) {
            unsigned aph[4], apl[4];
            bfsplit2(s[2 * c16][0],     s[2 * c16][1],     aph[0], apl[0]);
            bfsplit2(s[2 * c16][2],     s[2 * c16][3],     aph[1], apl[1]);
            bfsplit2(s[2 * c16 + 1][0], s[2 * c16 + 1][1], aph[2], apl[2]);
            bfsplit2(s[2 * c16 + 1][2], s[2 * c16 + 1][3], aph[3], apl[3]);
            const unsigned vro = (unsigned)((c16 * 16 + v_row) * 144 + v_co * 2);
#pragma unroll
            for (int njp = 0; njp < 4; ++njp) {
                const unsigned voff = vro + (unsigned)(njp * 32);
                unsigned vh[4], vl[4];
                ldsm_x4t(vh[0], vh[1], vh[2], vh[3], sbase + AVH + voff);
                ldsm_x4t(vl[0], vl[1], vl[2], vl[3], sbase + AVL + voff);
                mma_bf16(o[2 * njp],     aph, vh + 0);
                mma_bf16(o[2 * njp],     aph, vl + 0);
                mma_bf16(o[2 * njp],     apl, vh + 0);
                mma_bf16(o[2 * njp + 1], aph, vh + 2);
                mma_bf16(o[2 * njp + 1], aph, vl + 2);
                mma_bf16(o[2 * njp + 1], apl, vh + 2);
            }
        }
    }

    // Epilogue: normalize, write to g_O [B,N,EMBED].
    const int h  = bh & (HEADS - 1);
    const int b  = bh >> 4;
    const float inv0 = 1.0f / lrow[0];
    const float inv1 = 1.0f / lrow[1];
    const int r0 = q0 + arow + g;
#pragma unroll
    for (int nj = 0; nj < 8; ++nj) {
        const int col = h * HDIM + nj * 8 + 2 * t;
        float2 v0 = make_float2(o[nj][0] * inv0, o[nj][1] * inv0);
        *(float2*)&g_O[(size_t)(b * SEQ + r0) * EMBED + col] = v0;
        float2 v1 = make_float2(o[nj][2] * inv1, o[nj][3] * inv1);
        *(float2*)&g_O[(size_t)(b * SEQ + r0 + 8) * EMBED + col] = v1;
    }
}

// ---------------------------------------------------------------------------
extern "C" void kernel_launch(void* const* d_in, const int* in_sizes, int n_in,
                              void* d_out, int out_size)
{
    const float* x      = (const float*)d_in[0];
    const float* w_qkv  = (const float*)d_in[1];
    const float* b_qkv  = (const float*)d_in[2];
    const float* w_proj = (const float*)d_in[3];
    const float* b_proj = (const float*)d_in[4];
    float* out = (float*)d_out;

    float* gO = nullptr;
    cudaGetSymbolAddress((void**)&gO, g_O);

    static bool attr_set = false;
    if (!attr_set) {
        cudaFuncSetAttribute(flash_attn_mma,
                             cudaFuncAttributeMaxDynamicSharedMemorySize, SM_BYTES);
        attr_set = true;
    }

    // 1) QKV projection (tf32 mma) -> g_Q/g_K/g_V
    {
        dim3 grid(QKVN / 128, MTOK / 128);
        gemm_mma<0><<<grid, 256>>>(x, w_qkv, b_qkv, nullptr, MTOK, QKVN, EMBED);
    }
    // 2) Flash attention (bf16-split S + register-P PV) -> g_O
    {
        dim3 grid(SEQ / 128, BATCH * HEADS);
        flash_attn_mma<<<grid, 256, SM_BYTES>>>();
    }
    // 3) Output projection (tf32 mma)
    {
        dim3 grid(EMBED / 128, MTOK / 128);
        gemm_mma<1><<<grid, 256>>>(gO, w_proj, b_proj, out, MTOK, EMBED, EMBED);
    }
}